// round 1
// baseline (speedup 1.0000x reference)
#include <cuda_runtime.h>
#include <cstdint>

// Problem constants
#define BB   8
#define LL   4096
#define DD   768
#define NE   64     // N (state dim)
#define KC   4      // conv kernel
#define PP   64
#define DIc  1536   // DI
#define HHc  24     // H
#define CDc  1664   // CD
#define DIPc 3224   // DIP
#define MROWS (BB*LL)   // 32768

// ---------------- workspace (static __device__, no allocations) ----------------
__device__ float g_xn[(size_t)MROWS*DD];        // 100 MB
__device__ float g_zx[(size_t)MROWS*DIPc];      // 422 MB
__device__ float g_xbc[(size_t)MROWS*CDc];      // 218 MB
__device__ float g_dt[(size_t)MROWS*HHc];
__device__ float g_dA[(size_t)MROWS*HHc];
__device__ float g_y[(size_t)MROWS*DIc];        // 201 MB (reused in-place by gate)

// ---------------- LayerNorm ----------------
__global__ void ln_kernel(const float* __restrict__ x,
                          const float* __restrict__ w,
                          const float* __restrict__ b) {
    int row = blockIdx.x;
    const float* xr = x + (size_t)row * DD;
    float s = 0.f, s2 = 0.f;
    for (int i = threadIdx.x; i < DD; i += 256) {
        float v = xr[i];
        s += v; s2 += v * v;
    }
    __shared__ float red0[8], red1[8];
    for (int o = 16; o; o >>= 1) {
        s  += __shfl_xor_sync(0xffffffffu, s,  o);
        s2 += __shfl_xor_sync(0xffffffffu, s2, o);
    }
    int warp = threadIdx.x >> 5, lane = threadIdx.x & 31;
    if (lane == 0) { red0[warp] = s; red1[warp] = s2; }
    __syncthreads();
    if (warp == 0) {
        s  = (lane < 8) ? red0[lane] : 0.f;
        s2 = (lane < 8) ? red1[lane] : 0.f;
        for (int o = 4; o; o >>= 1) {
            s  += __shfl_xor_sync(0xffffffffu, s,  o);
            s2 += __shfl_xor_sync(0xffffffffu, s2, o);
        }
        if (lane == 0) { red0[0] = s; red1[0] = s2; }
    }
    __syncthreads();
    float mu  = red0[0] * (1.f / DD);
    float var = red1[0] * (1.f / DD) - mu * mu;
    float rs  = rsqrtf(var + 1e-5f);
    float* o = g_xn + (size_t)row * DD;
    for (int i = threadIdx.x; i < DD; i += 256)
        o[i] = (xr[i] - mu) * rs * w[i] + b[i];
}

// ---------------- tf32 GEMM (mma.sync m16n8k8) ----------------
__device__ __forceinline__ uint32_t f2tf(float f) {
    uint32_t r;
    asm("cvt.rna.tf32.f32 %0, %1;" : "=r"(r) : "f"(f));
    return r;
}

__device__ __forceinline__ void mma_tf32(float c[4],
                                         uint32_t a0, uint32_t a1, uint32_t a2, uint32_t a3,
                                         uint32_t b0, uint32_t b1) {
    asm volatile(
        "mma.sync.aligned.m16n8k8.row.col.f32.tf32.tf32.f32 "
        "{%0,%1,%2,%3},{%4,%5,%6,%7},{%8,%9},{%0,%1,%2,%3};\n"
        : "+f"(c[0]), "+f"(c[1]), "+f"(c[2]), "+f"(c[3])
        : "r"(a0), "r"(a1), "r"(a2), "r"(a3), "r"(b0), "r"(b1));
}

// Out[m,n] = sum_k A[m,k] * W[n,k]   (+ Res[m,n] if ADDRES)
// A: row-major [M, KDIM]; W: row-major [Ntot_alloc, KDIM] (contiguous k per n)
template <int KDIM, bool ADDRES>
__global__ void __launch_bounds__(256) gemm_tf32(const float* __restrict__ A,
                                                 const float* __restrict__ W,
                                                 const float* __restrict__ Res,
                                                 float* __restrict__ Out,
                                                 int Ntot) {
    constexpr int BM = 128, BN = 128, BK = 32;
    constexpr int ASTR = BK + 4;   // 36: bank = 4*row + k -> conflict-free frag loads
    constexpr int BSTR = BN + 8;   // 136: bank = 8*k + n  -> conflict-free frag loads
    __shared__ uint32_t As[BM * ASTR];
    __shared__ uint32_t Bs[BK * BSTR];

    int tid = threadIdx.x;
    int bm0 = blockIdx.y * BM, bn0 = blockIdx.x * BN;
    int warp = tid >> 5, lane = tid & 31;
    int wm = (warp & 3) * 32, wn = (warp >> 2) * 64;
    int g = lane >> 2, tg = lane & 3;

    float acc[2][8][4];
#pragma unroll
    for (int i = 0; i < 2; i++)
#pragma unroll
        for (int j = 0; j < 8; j++)
#pragma unroll
            for (int k = 0; k < 4; k++) acc[i][j][k] = 0.f;

    int arow = tid >> 3;          // 0..31
    int acol = (tid & 7) * 4;     // 0..28
    int bn   = tid >> 1;          // 0..127
    int bkh  = (tid & 1) * 16;    // 0 or 16

    for (int kb = 0; kb < KDIM; kb += BK) {
        // stage A tile (128 x 32)
#pragma unroll
        for (int r = 0; r < 4; r++) {
            const float4 v = *reinterpret_cast<const float4*>(
                A + (size_t)(bm0 + arow + r * 32) * KDIM + kb + acol);
            uint32_t* dst = &As[(arow + r * 32) * ASTR + acol];
            dst[0] = f2tf(v.x); dst[1] = f2tf(v.y);
            dst[2] = f2tf(v.z); dst[3] = f2tf(v.w);
        }
        // stage B tile (32 x 128), B[k][n] = W[n][k]
        {
            int n = bn0 + bn;
            if (n < Ntot) {
                const float* src = W + (size_t)n * KDIM + kb + bkh;
#pragma unroll
                for (int r = 0; r < 4; r++) {
                    float4 v = *reinterpret_cast<const float4*>(src + r * 4);
                    Bs[(bkh + r * 4 + 0) * BSTR + bn] = f2tf(v.x);
                    Bs[(bkh + r * 4 + 1) * BSTR + bn] = f2tf(v.y);
                    Bs[(bkh + r * 4 + 2) * BSTR + bn] = f2tf(v.z);
                    Bs[(bkh + r * 4 + 3) * BSTR + bn] = f2tf(v.w);
                }
            } else {
#pragma unroll
                for (int r = 0; r < 16; r++) Bs[(bkh + r) * BSTR + bn] = 0u;
            }
        }
        __syncthreads();
#pragma unroll
        for (int ks = 0; ks < 4; ks++) {
            int k0 = ks * 8;
            uint32_t a[2][4], b[8][2];
#pragma unroll
            for (int mt = 0; mt < 2; mt++) {
                int r0 = wm + mt * 16;
                a[mt][0] = As[(r0 + g    ) * ASTR + k0 + tg    ];
                a[mt][1] = As[(r0 + g + 8) * ASTR + k0 + tg    ];
                a[mt][2] = As[(r0 + g    ) * ASTR + k0 + tg + 4];
                a[mt][3] = As[(r0 + g + 8) * ASTR + k0 + tg + 4];
            }
#pragma unroll
            for (int nt = 0; nt < 8; nt++) {
                int c = wn + nt * 8 + g;
                b[nt][0] = Bs[(k0 + tg    ) * BSTR + c];
                b[nt][1] = Bs[(k0 + tg + 4) * BSTR + c];
            }
#pragma unroll
            for (int mt = 0; mt < 2; mt++)
#pragma unroll
                for (int nt = 0; nt < 8; nt++)
                    mma_tf32(acc[mt][nt], a[mt][0], a[mt][1], a[mt][2], a[mt][3],
                             b[nt][0], b[nt][1]);
        }
        __syncthreads();
    }

    // epilogue
#pragma unroll
    for (int mt = 0; mt < 2; mt++) {
        int r0 = bm0 + wm + mt * 16 + g;
#pragma unroll
        for (int nt = 0; nt < 8; nt++) {
            int c0 = bn0 + wn + nt * 8 + tg * 2;
            if (c0 < Ntot) {
                float* o0 = Out + (size_t)r0 * Ntot + c0;
                float* o1 = Out + (size_t)(r0 + 8) * Ntot + c0;
                if (ADDRES) {
                    const float* x0 = Res + (size_t)r0 * Ntot + c0;
                    const float* x1 = Res + (size_t)(r0 + 8) * Ntot + c0;
                    o0[0] = acc[mt][nt][0] + x0[0];
                    o0[1] = acc[mt][nt][1] + x0[1];
                    o1[0] = acc[mt][nt][2] + x1[0];
                    o1[1] = acc[mt][nt][3] + x1[1];
                } else {
                    o0[0] = acc[mt][nt][0];
                    o0[1] = acc[mt][nt][1];
                    o1[0] = acc[mt][nt][2];
                    o1[1] = acc[mt][nt][3];
                }
            }
        }
    }
}

// ---------------- depthwise causal conv(K=4) + SiLU ----------------
__global__ void conv_kernel(const float* __restrict__ cw,
                            const float* __restrict__ cb) {
    long idx = (long)blockIdx.x * 256 + threadIdx.x;
    if (idx >= (long)MROWS * CDc) return;
    int c = (int)(idx % CDc);
    long rl = idx / CDc;
    int l = (int)(rl % LL);
    long b = rl / LL;
    float s = cb[c];
#pragma unroll
    for (int j = 0; j < KC; j++) {
        int lj = l - (KC - 1) + j;
        if (lj >= 0)
            s += g_zx[(b * LL + lj) * (size_t)DIPc + DIc + c] * cw[c * KC + j];
    }
    float sig = 1.f / (1.f + expf(-s));
    g_xbc[idx] = s * sig;
}

// ---------------- dt: softplus, dA ----------------
__global__ void dt_kernel(const float* __restrict__ dt_bias,
                          const float* __restrict__ A_log) {
    int idx = blockIdx.x * 256 + threadIdx.x;
    if (idx >= MROWS * HHc) return;
    int h = idx % HHc;
    int row = idx / HHc;
    float raw = g_zx[(size_t)row * DIPc + DIc + CDc + h] + dt_bias[h];
    float dt = (raw > 20.f) ? raw : log1pf(expf(raw));
    g_dt[idx] = dt;
    g_dA[idx] = expf(-expf(A_log[h]) * dt);
}

// ---------------- sequential selective scan ----------------
// grid: B*H*2 blocks; block handles (b, h, p-half of 32). 256 threads:
// thread = (p_local = tid>>3) x (n-chunk of 8 = tid&7). State 8 floats/thread.
__global__ void __launch_bounds__(256) scan_kernel(const float* __restrict__ D_skip) {
    int bx = blockIdx.x;
    int b  = bx / (HHc * 2);
    int rem = bx % (HHc * 2);
    int h  = rem >> 1;
    int ph = rem & 1;
    int tid = threadIdx.x;
    int pl = tid >> 3;
    int q  = tid & 7;
    int n0 = q * 8;

    __shared__ float sx[32][33];
    __shared__ float sB[32][64];
    __shared__ float sC[32][64];
    __shared__ float sy[32][32];
    __shared__ float sdA[32], sdt[32];

    float hreg[8];
#pragma unroll
    for (int j = 0; j < 8; j++) hreg[j] = 0.f;

    float ds = D_skip[h];
    size_t rowbase = (size_t)b * LL;
    int pcol = h * PP + ph * 32;   // column in xbc (xs region) and in y

    for (int l0 = 0; l0 < LL; l0 += 32) {
        // stage 32 steps
        for (int i = tid; i < 32 * 32; i += 256) {
            int s = i >> 5, j = i & 31;
            sx[s][j] = g_xbc[(rowbase + l0 + s) * CDc + pcol + j];
        }
        for (int i = tid; i < 32 * 64; i += 256) {
            int s = i >> 6, j = i & 63;
            sB[s][j] = g_xbc[(rowbase + l0 + s) * CDc + DIc + j];
            sC[s][j] = g_xbc[(rowbase + l0 + s) * CDc + DIc + NE + j];
        }
        if (tid < 32) {
            sdA[tid] = g_dA[(rowbase + l0 + tid) * HHc + h];
            sdt[tid] = g_dt[(rowbase + l0 + tid) * HHc + h];
        }
        __syncthreads();

#pragma unroll 4
        for (int s = 0; s < 32; s++) {
            float a  = sdA[s];
            float d  = sdt[s];
            float xv = sx[s][pl];
            float u  = d * xv;
            float4 b0 = *reinterpret_cast<const float4*>(&sB[s][n0]);
            float4 b1 = *reinterpret_cast<const float4*>(&sB[s][n0 + 4]);
            float4 c0 = *reinterpret_cast<const float4*>(&sC[s][n0]);
            float4 c1 = *reinterpret_cast<const float4*>(&sC[s][n0 + 4]);
            float acc = 0.f;
            hreg[0] = hreg[0] * a + u * b0.x; acc += hreg[0] * c0.x;
            hreg[1] = hreg[1] * a + u * b0.y; acc += hreg[1] * c0.y;
            hreg[2] = hreg[2] * a + u * b0.z; acc += hreg[2] * c0.z;
            hreg[3] = hreg[3] * a + u * b0.w; acc += hreg[3] * c0.w;
            hreg[4] = hreg[4] * a + u * b1.x; acc += hreg[4] * c1.x;
            hreg[5] = hreg[5] * a + u * b1.y; acc += hreg[5] * c1.y;
            hreg[6] = hreg[6] * a + u * b1.z; acc += hreg[6] * c1.z;
            hreg[7] = hreg[7] * a + u * b1.w; acc += hreg[7] * c1.w;
            acc += __shfl_xor_sync(0xffffffffu, acc, 1);
            acc += __shfl_xor_sync(0xffffffffu, acc, 2);
            acc += __shfl_xor_sync(0xffffffffu, acc, 4);
            if (q == 0) sy[s][pl] = acc + ds * xv;
        }
        __syncthreads();
        for (int i = tid; i < 32 * 32; i += 256) {
            int s = i >> 5, j = i & 31;
            g_y[(rowbase + l0 + s) * DIc + pcol + j] = sy[s][j];
        }
        __syncthreads();
    }
}

// ---------------- gate (y * silu(z)) + RMSNorm, in-place on g_y ----------------
__global__ void gate_kernel(const float* __restrict__ norm_w) {
    int row = blockIdx.x;
    int tid = threadIdx.x;
    const float* z = g_zx + (size_t)row * DIPc;
    float* y = g_y + (size_t)row * DIc;
    float t[6];
    float s2 = 0.f;
#pragma unroll
    for (int r = 0; r < 6; r++) {
        int i = tid + r * 256;
        float zz = z[i];
        float sig = 1.f / (1.f + expf(-zz));
        float v = y[i] * zz * sig;
        t[r] = v;
        s2 += v * v;
    }
    __shared__ float red[8];
    for (int o = 16; o; o >>= 1) s2 += __shfl_xor_sync(0xffffffffu, s2, o);
    int warp = tid >> 5, lane = tid & 31;
    if (lane == 0) red[warp] = s2;
    __syncthreads();
    if (warp == 0) {
        s2 = (lane < 8) ? red[lane] : 0.f;
        for (int o = 4; o; o >>= 1) s2 += __shfl_xor_sync(0xffffffffu, s2, o);
        if (lane == 0) red[0] = s2;
    }
    __syncthreads();
    float scale = rsqrtf(red[0] * (1.f / DIc) + 1e-5f);
#pragma unroll
    for (int r = 0; r < 6; r++) {
        int i = tid + r * 256;
        y[i] = t[r] * scale * norm_w[i];
    }
}

// ---------------- launch ----------------
extern "C" void kernel_launch(void* const* d_in, const int* in_sizes, int n_in,
                              void* d_out, int out_size) {
    const float* x       = (const float*)d_in[0];
    const float* ln_w    = (const float*)d_in[1];
    const float* ln_b    = (const float*)d_in[2];
    const float* Win     = (const float*)d_in[3];
    const float* conv_w  = (const float*)d_in[4];
    const float* conv_b  = (const float*)d_in[5];
    const float* dt_bias = (const float*)d_in[6];
    const float* A_log   = (const float*)d_in[7];
    const float* D_skip  = (const float*)d_in[8];
    const float* norm_w  = (const float*)d_in[9];
    const float* Wout    = (const float*)d_in[10];
    float* out = (float*)d_out;

    float* zx_ptr = nullptr; cudaGetSymbolAddress((void**)&zx_ptr, g_zx);
    float* xn_ptr = nullptr; cudaGetSymbolAddress((void**)&xn_ptr, g_xn);
    float* y_ptr  = nullptr; cudaGetSymbolAddress((void**)&y_ptr,  g_y);

    // 1. LayerNorm
    ln_kernel<<<MROWS, 256>>>(x, ln_w, ln_b);
    // 2. zxbcdt = xn @ Win^T   (M=32768, K=768, N=3224)
    gemm_tf32<DD, false><<<dim3((DIPc + 127) / 128, MROWS / 128), 256>>>(
        xn_ptr, Win, nullptr, zx_ptr, DIPc);
    // 3. depthwise causal conv + silu
    {
        long total = (long)MROWS * CDc;
        conv_kernel<<<(unsigned)((total + 255) / 256), 256>>>(conv_w, conv_b);
    }
    // 4. dt / dA
    dt_kernel<<<(MROWS * HHc + 255) / 256, 256>>>(dt_bias, A_log);
    // 5. selective scan
    scan_kernel<<<BB * HHc * 2, 256>>>(D_skip);
    // 6. gate + RMSNorm (in-place on g_y)
    gate_kernel<<<MROWS, 256>>>(norm_w);
    // 7. out = g @ Wout^T + x  (M=32768, K=1536, N=768)
    gemm_tf32<DIc, true><<<dim3(DD / 128, MROWS / 128), 256>>>(
        y_ptr, Wout, x, out, DD);
}

// round 3
// speedup vs baseline: 1.2958x; 1.2958x over previous
#include <cuda_runtime.h>
#include <cuda_fp16.h>
#include <cstdint>

// Problem constants
#define BB   8
#define LL   4096
#define DD   768
#define NE   64
#define KC   4
#define PP   64
#define DIc  1536
#define HHc  24
#define CDc  1664
#define DIPc 3224
#define MROWS (BB*LL)   // 32768
#define NPAD1 3328      // DIP padded to 128-multiple

// ---------------- workspace ----------------
__device__ __half g_xnh[(size_t)MROWS*DD];     // LN out (half)
__device__ float  g_zx[(size_t)MROWS*DIPc];    // GEMM1 out (fp32)
__device__ float  g_xbc[(size_t)MROWS*CDc];    // conv+silu out
__device__ float  g_y[(size_t)MROWS*DIc];      // scan out (fp32)
__device__ __half g_gh[(size_t)MROWS*DIc];     // gate out (half)
__device__ __half g_w1h[(size_t)NPAD1*DD];     // Win half, padded rows
__device__ __half g_w2h[(size_t)DD*DIc];       // Wout half

// ---------------- helpers ----------------
__device__ __forceinline__ uint32_t smem_u32(const void* p) {
    uint32_t a;
    asm("{ .reg .u64 t; cvta.to.shared.u64 t, %1; cvt.u32.u64 %0, t; }" : "=r"(a) : "l"(p));
    return a;
}
__device__ __forceinline__ void cp16(uint32_t dst, const void* src) {
    asm volatile("cp.async.cg.shared.global [%0], [%1], 16;" :: "r"(dst), "l"(src));
}
#define CP_COMMIT() asm volatile("cp.async.commit_group;" ::: "memory")
#define CP_WAIT1()  asm volatile("cp.async.wait_group 1;" ::: "memory")

__device__ __forceinline__ void mma_f16(float c[4], uint32_t a0, uint32_t a1,
                                        uint32_t a2, uint32_t a3,
                                        uint32_t b0, uint32_t b1) {
    asm volatile(
        "mma.sync.aligned.m16n8k16.row.col.f32.f16.f16.f32 "
        "{%0,%1,%2,%3},{%4,%5,%6,%7},{%8,%9},{%0,%1,%2,%3};\n"
        : "+f"(c[0]), "+f"(c[1]), "+f"(c[2]), "+f"(c[3])
        : "r"(a0), "r"(a1), "r"(a2), "r"(a3), "r"(b0), "r"(b1));
}

// ---------------- fp16 GEMM: Out[m,n] = sum_k A[m,k]*W[n,k] (+Res) ----------------
// Tiles 128x128x32, 3-stage cp.async pipeline, 8 warps (4 m x 2 n), warp = 32x64.
static constexpr int GSTAGE = 20480;          // bytes per stage (A 10240 + B 10240)
static constexpr int GSMEM  = 3 * GSTAGE;     // 61440

template <int KDIM, bool ADDRES>
__global__ void __launch_bounds__(256, 2) gemm_h(const __half* __restrict__ A,
                                                 const __half* __restrict__ W,
                                                 const float* __restrict__ Res,
                                                 float* __restrict__ Out, int Ntot) {
    extern __shared__ char smem[];
    uint32_t sbase = smem_u32(smem);
    constexpr int KT = KDIM / 32;

    int tid = threadIdx.x;
    int bm0 = blockIdx.y * 128, bn0 = blockIdx.x * 128;
    int warp = tid >> 5, lane = tid & 31;
    int wm = (warp & 3) * 32, wn = (warp >> 2) * 64;
    int g = lane >> 2, tg = lane & 3;

    float acc[2][8][4];
#pragma unroll
    for (int i = 0; i < 2; i++)
#pragma unroll
        for (int j = 0; j < 8; j++)
#pragma unroll
            for (int k = 0; k < 4; k++) acc[i][j][k] = 0.f;

    // staging map: 256 threads, row = tid>>1 (0..127), co = (tid&1)*16 halfs
    int srow = tid >> 1;
    int sco  = (tid & 1) * 16;
    const __half* gA = A + (size_t)(bm0 + srow) * KDIM + sco;
    const __half* gB = W + (size_t)(bn0 + srow) * KDIM + sco;
    uint32_t dA = sbase + srow * 80 + sco * 2;
    uint32_t dB = dA + 10240;

#define LOAD_STAGE(s, t) do { \
        uint32_t so = (uint32_t)(s) * GSTAGE; \
        const __half* a = gA + (t) * 32; \
        const __half* b = gB + (t) * 32; \
        cp16(dA + so, a);      cp16(dA + so + 16, a + 8); \
        cp16(dB + so, b);      cp16(dB + so + 16, b + 8); \
    } while (0)

    LOAD_STAGE(0, 0); CP_COMMIT();
    LOAD_STAGE(1, 1); CP_COMMIT();

    for (int t = 0; t < KT; t++) {
        CP_WAIT1();
        __syncthreads();
        if (t + 2 < KT) { LOAD_STAGE((t + 2) % 3, t + 2); CP_COMMIT(); }

        const __half* Ah = (const __half*)(smem + (t % 3) * GSTAGE);
        const __half* Bh = Ah + 5120;
#pragma unroll
        for (int ks = 0; ks < 2; ks++) {
            int k0 = ks * 16;
            uint32_t a[2][4], b[8][2];
#pragma unroll
            for (int mt = 0; mt < 2; mt++) {
                const __half* p = Ah + (wm + mt * 16 + g) * 40 + k0 + tg * 2;
                a[mt][0] = *(const uint32_t*)(p);
                a[mt][1] = *(const uint32_t*)(p + 8 * 40);
                a[mt][2] = *(const uint32_t*)(p + 8);
                a[mt][3] = *(const uint32_t*)(p + 8 * 40 + 8);
            }
#pragma unroll
            for (int nt = 0; nt < 8; nt++) {
                const __half* p = Bh + (wn + nt * 8 + g) * 40 + k0 + tg * 2;
                b[nt][0] = *(const uint32_t*)(p);
                b[nt][1] = *(const uint32_t*)(p + 8);
            }
#pragma unroll
            for (int mt = 0; mt < 2; mt++)
#pragma unroll
                for (int nt = 0; nt < 8; nt++)
                    mma_f16(acc[mt][nt], a[mt][0], a[mt][1], a[mt][2], a[mt][3],
                            b[nt][0], b[nt][1]);
        }
        __syncthreads();
    }
#undef LOAD_STAGE

    // epilogue
#pragma unroll
    for (int mt = 0; mt < 2; mt++) {
        int r0 = bm0 + wm + mt * 16 + g;
#pragma unroll
        for (int nt = 0; nt < 8; nt++) {
            int c0 = bn0 + wn + nt * 8 + tg * 2;
            if (c0 < Ntot) {
                float2 v0 = make_float2(acc[mt][nt][0], acc[mt][nt][1]);
                float2 v1 = make_float2(acc[mt][nt][2], acc[mt][nt][3]);
                float* o0 = Out + (size_t)r0 * Ntot + c0;
                float* o1 = Out + (size_t)(r0 + 8) * Ntot + c0;
                if (ADDRES) {
                    float2 x0 = *(const float2*)(Res + (size_t)r0 * Ntot + c0);
                    float2 x1 = *(const float2*)(Res + (size_t)(r0 + 8) * Ntot + c0);
                    v0.x += x0.x; v0.y += x0.y;
                    v1.x += x1.x; v1.y += x1.y;
                }
                *(float2*)o0 = v0;
                *(float2*)o1 = v1;
            }
        }
    }
}

// ---------------- weight converts ----------------
__global__ void cvtW1(const float* __restrict__ W) {
    int idx = blockIdx.x * 256 + threadIdx.x;
    if (idx >= NPAD1 * DD) return;
    int r = idx / DD;
    g_w1h[idx] = (r < DIPc) ? __float2half(W[idx]) : __half(0.f);
}
__global__ void cvtW2(const float* __restrict__ W) {
    int idx = blockIdx.x * 256 + threadIdx.x;
    if (idx >= DD * DIc) return;
    g_w2h[idx] = __float2half(W[idx]);
}

// ---------------- LayerNorm (half out) ----------------
__global__ void ln_kernel(const float* __restrict__ x,
                          const float* __restrict__ w,
                          const float* __restrict__ b) {
    int row = blockIdx.x;
    const float* xr = x + (size_t)row * DD;
    float s = 0.f, s2 = 0.f;
    for (int i = threadIdx.x; i < DD; i += 256) {
        float v = xr[i];
        s += v; s2 += v * v;
    }
    __shared__ float red0[8], red1[8];
    for (int o = 16; o; o >>= 1) {
        s  += __shfl_xor_sync(0xffffffffu, s,  o);
        s2 += __shfl_xor_sync(0xffffffffu, s2, o);
    }
    int warp = threadIdx.x >> 5, lane = threadIdx.x & 31;
    if (lane == 0) { red0[warp] = s; red1[warp] = s2; }
    __syncthreads();
    if (warp == 0) {
        s  = (lane < 8) ? red0[lane] : 0.f;
        s2 = (lane < 8) ? red1[lane] : 0.f;
        for (int o = 4; o; o >>= 1) {
            s  += __shfl_xor_sync(0xffffffffu, s,  o);
            s2 += __shfl_xor_sync(0xffffffffu, s2, o);
        }
        if (lane == 0) { red0[0] = s; red1[0] = s2; }
    }
    __syncthreads();
    float mu  = red0[0] * (1.f / DD);
    float var = red1[0] * (1.f / DD) - mu * mu;
    float rs  = rsqrtf(var + 1e-5f);
    __half* o = g_xnh + (size_t)row * DD;
    for (int i = threadIdx.x; i < DD; i += 256)
        o[i] = __float2half((xr[i] - mu) * rs * w[i] + b[i]);
}

// ---------------- depthwise causal conv(K=4) + SiLU ----------------
__global__ void conv_kernel(const float* __restrict__ cw,
                            const float* __restrict__ cb) {
    long idx = (long)blockIdx.x * 256 + threadIdx.x;
    if (idx >= (long)MROWS * CDc) return;
    int c = (int)(idx % CDc);
    long rl = idx / CDc;
    int l = (int)(rl % LL);
    long b = rl / LL;
    float s = cb[c];
#pragma unroll
    for (int j = 0; j < KC; j++) {
        int lj = l - (KC - 1) + j;
        if (lj >= 0)
            s += g_zx[(b * LL + lj) * (size_t)DIPc + DIc + c] * cw[c * KC + j];
    }
    float sig = 1.f / (1.f + expf(-s));
    g_xbc[idx] = s * sig;
}

// ---------------- selective scan (dt/dA fused) ----------------
__global__ void __launch_bounds__(256) scan_kernel(const float* __restrict__ D_skip,
                                                   const float* __restrict__ dt_bias,
                                                   const float* __restrict__ A_log) {
    int bx = blockIdx.x;
    int b  = bx / (HHc * 2);
    int rem = bx % (HHc * 2);
    int h  = rem >> 1;
    int ph = rem & 1;
    int tid = threadIdx.x;
    int pl = tid >> 3;
    int q  = tid & 7;
    int n0 = q * 8;

    __shared__ float sx[32][33];
    __shared__ float sB[32][64];
    __shared__ float sC[32][64];
    __shared__ float sy[32][32];
    __shared__ float sdA[32], sdt[32];

    float hreg[8];
#pragma unroll
    for (int j = 0; j < 8; j++) hreg[j] = 0.f;

    float ds = D_skip[h];
    float aexp = expf(A_log[h]);
    float dbias = dt_bias[h];
    size_t rowbase = (size_t)b * LL;
    int pcol = h * PP + ph * 32;

    for (int l0 = 0; l0 < LL; l0 += 32) {
        for (int i = tid; i < 32 * 32; i += 256) {
            int s = i >> 5, j = i & 31;
            sx[s][j] = g_xbc[(rowbase + l0 + s) * CDc + pcol + j];
        }
        for (int i = tid; i < 32 * 64; i += 256) {
            int s = i >> 6, j = i & 63;
            sB[s][j] = g_xbc[(rowbase + l0 + s) * CDc + DIc + j];
            sC[s][j] = g_xbc[(rowbase + l0 + s) * CDc + DIc + NE + j];
        }
        if (tid < 32) {
            float raw = g_zx[(rowbase + l0 + tid) * DIPc + (DIc + CDc) + h] + dbias;
            float dtv = (raw > 20.f) ? raw : log1pf(expf(raw));
            sdt[tid] = dtv;
            sdA[tid] = expf(-aexp * dtv);
        }
        __syncthreads();

#pragma unroll 4
        for (int s = 0; s < 32; s++) {
            float a  = sdA[s];
            float d  = sdt[s];
            float xv = sx[s][pl];
            float u  = d * xv;
            float4 b0 = *reinterpret_cast<const float4*>(&sB[s][n0]);
            float4 b1 = *reinterpret_cast<const float4*>(&sB[s][n0 + 4]);
            float4 c0 = *reinterpret_cast<const float4*>(&sC[s][n0]);
            float4 c1 = *reinterpret_cast<const float4*>(&sC[s][n0 + 4]);
            float acc = 0.f;
            hreg[0] = hreg[0] * a + u * b0.x; acc += hreg[0] * c0.x;
            hreg[1] = hreg[1] * a + u * b0.y; acc += hreg[1] * c0.y;
            hreg[2] = hreg[2] * a + u * b0.z; acc += hreg[2] * c0.z;
            hreg[3] = hreg[3] * a + u * b0.w; acc += hreg[3] * c0.w;
            hreg[4] = hreg[4] * a + u * b1.x; acc += hreg[4] * c1.x;
            hreg[5] = hreg[5] * a + u * b1.y; acc += hreg[5] * c1.y;
            hreg[6] = hreg[6] * a + u * b1.z; acc += hreg[6] * c1.z;
            hreg[7] = hreg[7] * a + u * b1.w; acc += hreg[7] * c1.w;
            acc += __shfl_xor_sync(0xffffffffu, acc, 1);
            acc += __shfl_xor_sync(0xffffffffu, acc, 2);
            acc += __shfl_xor_sync(0xffffffffu, acc, 4);
            if (q == 0) sy[s][pl] = acc + ds * xv;
        }
        __syncthreads();
        for (int i = tid; i < 32 * 32; i += 256) {
            int s = i >> 5, j = i & 31;
            g_y[(rowbase + l0 + s) * DIc + pcol + j] = sy[s][j];
        }
        __syncthreads();
    }
}

// ---------------- gate + RMSNorm (half out) ----------------
__global__ void gate_kernel(const float* __restrict__ norm_w) {
    int row = blockIdx.x;
    int tid = threadIdx.x;
    const float* z = g_zx + (size_t)row * DIPc;
    const float* y = g_y + (size_t)row * DIc;
    __half* o = g_gh + (size_t)row * DIc;
    float t[6];
    float s2 = 0.f;
#pragma unroll
    for (int r = 0; r < 6; r++) {
        int i = tid + r * 256;
        float zz = z[i];
        float sig = 1.f / (1.f + expf(-zz));
        float v = y[i] * zz * sig;
        t[r] = v;
        s2 += v * v;
    }
    __shared__ float red[8];
    for (int o2 = 16; o2; o2 >>= 1) s2 += __shfl_xor_sync(0xffffffffu, s2, o2);
    int warp = tid >> 5, lane = tid & 31;
    if (lane == 0) red[warp] = s2;
    __syncthreads();
    if (warp == 0) {
        s2 = (lane < 8) ? red[lane] : 0.f;
        for (int o2 = 4; o2; o2 >>= 1) s2 += __shfl_xor_sync(0xffffffffu, s2, o2);
        if (lane == 0) red[0] = s2;
    }
    __syncthreads();
    float scale = rsqrtf(red[0] * (1.f / DIc) + 1e-5f);
#pragma unroll
    for (int r = 0; r < 6; r++) {
        int i = tid + r * 256;
        o[i] = __float2half(t[r] * scale * norm_w[i]);
    }
}

// ---------------- launch ----------------
extern "C" void kernel_launch(void* const* d_in, const int* in_sizes, int n_in,
                              void* d_out, int out_size) {
    const float* x       = (const float*)d_in[0];
    const float* ln_w    = (const float*)d_in[1];
    const float* ln_b    = (const float*)d_in[2];
    const float* Win     = (const float*)d_in[3];
    const float* conv_w  = (const float*)d_in[4];
    const float* conv_b  = (const float*)d_in[5];
    const float* dt_bias = (const float*)d_in[6];
    const float* A_log   = (const float*)d_in[7];
    const float* D_skip  = (const float*)d_in[8];
    const float* norm_w  = (const float*)d_in[9];
    const float* Wout    = (const float*)d_in[10];
    float* out = (float*)d_out;

    float*  zx_ptr  = nullptr; cudaGetSymbolAddress((void**)&zx_ptr,  g_zx);
    __half* xnh_ptr = nullptr; cudaGetSymbolAddress((void**)&xnh_ptr, g_xnh);
    __half* gh_ptr  = nullptr; cudaGetSymbolAddress((void**)&gh_ptr,  g_gh);
    __half* w1h_ptr = nullptr; cudaGetSymbolAddress((void**)&w1h_ptr, g_w1h);
    __half* w2h_ptr = nullptr; cudaGetSymbolAddress((void**)&w2h_ptr, g_w2h);

    cudaFuncSetAttribute((const void*)gemm_h<DD,  false>,
                         cudaFuncAttributeMaxDynamicSharedMemorySize, GSMEM);
    cudaFuncSetAttribute((const void*)gemm_h<DIc, true>,
                         cudaFuncAttributeMaxDynamicSharedMemorySize, GSMEM);

    // 0-1. weight convert (half, pad Win rows to 3328)
    cvtW1<<<(NPAD1 * DD + 255) / 256, 256>>>(Win);
    cvtW2<<<(DD * DIc + 255) / 256, 256>>>(Wout);
    // 2. LayerNorm (half out)
    ln_kernel<<<MROWS, 256>>>(x, ln_w, ln_b);
    // 3. GEMM1: zxbcdt = xn @ Win^T  (M=32768, K=768, N=3224)
    gemm_h<DD, false><<<dim3(NPAD1 / 128, MROWS / 128), 256, GSMEM>>>(
        xnh_ptr, w1h_ptr, nullptr, zx_ptr, DIPc);
    // 4. conv + silu
    {
        long total = (long)MROWS * CDc;
        conv_kernel<<<(unsigned)((total + 255) / 256), 256>>>(conv_w, conv_b);
    }
    // 5. selective scan (dt fused)
    scan_kernel<<<BB * HHc * 2, 256>>>(D_skip, dt_bias, A_log);
    // 6. gate + RMSNorm (half out)
    gate_kernel<<<MROWS, 256>>>(norm_w);
    // 7. GEMM2: out = g @ Wout^T + x  (M=32768, K=1536, N=768)
    gemm_h<DIc, true><<<dim3(DD / 128, MROWS / 128), 256, GSMEM>>>(
        gh_ptr, w2h_ptr, x, out, DD);
}

// round 4
// speedup vs baseline: 1.3912x; 1.0736x over previous
#include <cuda_runtime.h>
#include <cuda_fp16.h>
#include <cstdint>

// Problem constants
#define BB   8
#define LL   4096
#define DD   768
#define NE   64
#define KC   4
#define PP   64
#define DIc  1536
#define HHc  24
#define CDc  1664
#define DIPc 3224
#define MROWS (BB*LL)   // 32768
#define NPAD1 3328      // DIP padded to 128-multiple

// ---------------- workspace ----------------
__device__ __half g_xnh[(size_t)MROWS*DD];     // LN out (half)
__device__ float  g_zx[(size_t)MROWS*DIPc];    // GEMM1 out (fp32)
__device__ float  g_xbc[(size_t)MROWS*CDc];    // conv+silu out
__device__ float  g_y[(size_t)MROWS*DIc];      // scan out (fp32)
__device__ __half g_gh[(size_t)MROWS*DIc];     // gate out (half)
__device__ __half g_w1h[(size_t)NPAD1*DD];     // Win half, padded rows
__device__ __half g_w2h[(size_t)DD*DIc];       // Wout half

// ---------------- helpers ----------------
__device__ __forceinline__ uint32_t smem_u32(const void* p) {
    uint32_t a;
    asm("{ .reg .u64 t; cvta.to.shared.u64 t, %1; cvt.u32.u64 %0, t; }" : "=r"(a) : "l"(p));
    return a;
}
__device__ __forceinline__ void cp16(uint32_t dst, const void* src) {
    asm volatile("cp.async.cg.shared.global [%0], [%1], 16;" :: "r"(dst), "l"(src));
}
#define CP_COMMIT() asm volatile("cp.async.commit_group;" ::: "memory")
#define CP_WAIT1()  asm volatile("cp.async.wait_group 1;" ::: "memory")

__device__ __forceinline__ void ldsm4(uint32_t r[4], uint32_t addr) {
    asm volatile("ldmatrix.sync.aligned.m8n8.x4.shared.b16 {%0,%1,%2,%3}, [%4];"
        : "=r"(r[0]), "=r"(r[1]), "=r"(r[2]), "=r"(r[3]) : "r"(addr));
}

__device__ __forceinline__ void mma_f16(float c[4], const uint32_t a[4],
                                        uint32_t b0, uint32_t b1) {
    asm volatile(
        "mma.sync.aligned.m16n8k16.row.col.f32.f16.f16.f32 "
        "{%0,%1,%2,%3},{%4,%5,%6,%7},{%8,%9},{%0,%1,%2,%3};\n"
        : "+f"(c[0]), "+f"(c[1]), "+f"(c[2]), "+f"(c[3])
        : "r"(a[0]), "r"(a[1]), "r"(a[2]), "r"(a[3]), "r"(b0), "r"(b1));
}

// ---------------- fp16 GEMM: Out[m,n] = sum_k A[m,k]*W[n,k] (+Res) ----------------
// Tiles 128x128x64; swizzled smem (128B rows, chunk^=(row&7)); ldmatrix.x4 frags;
// 3-stage cp.async pipeline; 8 warps (2 m x 4 n), warp tile = 64m x 32n.
static constexpr int GSTAGE = 32768;          // A 16KB + B 16KB per stage
static constexpr int GSMEM  = 3 * GSTAGE;     // 98304

template <int KDIM, bool ADDRES>
__global__ void __launch_bounds__(256, 2) gemm_h(const __half* __restrict__ A,
                                                 const __half* __restrict__ W,
                                                 const float* __restrict__ Res,
                                                 float* __restrict__ Out, int Ntot) {
    extern __shared__ char smem[];
    uint32_t sbase = smem_u32(smem);
    constexpr int KT = KDIM / 64;

    int tid = threadIdx.x;
    int bm0 = blockIdx.y * 128, bn0 = blockIdx.x * 128;
    int warp = tid >> 5, lane = tid & 31;
    int wm = (warp & 1) * 64, wn = (warp >> 1) * 32;
    int g = lane >> 2, tg = lane & 3;

    float acc[4][4][4];
#pragma unroll
    for (int i = 0; i < 4; i++)
#pragma unroll
        for (int j = 0; j < 4; j++)
#pragma unroll
            for (int k = 0; k < 4; k++) acc[i][j][k] = 0.f;

    // staging map: thread t -> row t>>1 (0..127), chunks (t&1)*4 .. +3 (16B each)
    int srow = tid >> 1;
    int scb  = (tid & 1) * 4;
    int sswz = srow & 7;
    const __half* gA = A + (size_t)(bm0 + srow) * KDIM + scb * 8;
    const __half* gB = W + (size_t)(bn0 + srow) * KDIM + scb * 8;
    uint32_t stA = sbase + srow * 128;
    uint32_t stB = stA + 16384;

#define LOAD_STAGE(s, t) do { \
        uint32_t so = (uint32_t)(s) * GSTAGE; \
        const __half* a = gA + (t) * 64; \
        const __half* b = gB + (t) * 64; \
        _Pragma("unroll") \
        for (int i = 0; i < 4; i++) { \
            uint32_t off = (uint32_t)(((scb + i) ^ sswz) * 16); \
            cp16(stA + so + off, a + i * 8); \
            cp16(stB + so + off, b + i * 8); \
        } \
    } while (0)

    LOAD_STAGE(0, 0); CP_COMMIT();
    LOAD_STAGE(1, 1); CP_COMMIT();

    // ldmatrix lane addressing (row part constant per lane; swizzle sel constant
    // across 16-row tile steps since 16 is a multiple of 8)
    int arow = wm + (lane & 15);
    int aks  = lane >> 4;            // 0/1 -> chunk +0/+1 within k16
    int aswz = arow & 7;
    int brow = wn + ((lane >> 4) << 3) + (lane & 7);
    int bks  = (lane >> 3) & 1;
    int bswz = brow & 7;

    for (int t = 0; t < KT; t++) {
        CP_WAIT1();
        __syncthreads();
        if (t + 2 < KT) { LOAD_STAGE((t + 2) % 3, t + 2); CP_COMMIT(); }

        uint32_t Abase = sbase + (uint32_t)(t % 3) * GSTAGE;
        uint32_t Bbase = Abase + 16384;
#pragma unroll
        for (int ks = 0; ks < 4; ks++) {
            uint32_t a[4][4], bb[2][4];
#pragma unroll
            for (int mt = 0; mt < 4; mt++)
                ldsm4(a[mt], Abase + (arow + mt * 16) * 128 +
                              (uint32_t)(((ks * 2 + aks) ^ aswz) * 16));
#pragma unroll
            for (int np = 0; np < 2; np++)
                ldsm4(bb[np], Bbase + (brow + np * 16) * 128 +
                               (uint32_t)(((ks * 2 + bks) ^ bswz) * 16));
#pragma unroll
            for (int mt = 0; mt < 4; mt++)
#pragma unroll
                for (int nt = 0; nt < 4; nt++)
                    mma_f16(acc[mt][nt], a[mt],
                            bb[nt >> 1][(nt & 1) * 2], bb[nt >> 1][(nt & 1) * 2 + 1]);
        }
        __syncthreads();
    }
#undef LOAD_STAGE

    // epilogue
#pragma unroll
    for (int mt = 0; mt < 4; mt++) {
        int r0 = bm0 + wm + mt * 16 + g;
#pragma unroll
        for (int nt = 0; nt < 4; nt++) {
            int c0 = bn0 + wn + nt * 8 + tg * 2;
            if (c0 < Ntot) {
                float2 v0 = make_float2(acc[mt][nt][0], acc[mt][nt][1]);
                float2 v1 = make_float2(acc[mt][nt][2], acc[mt][nt][3]);
                float* o0 = Out + (size_t)r0 * Ntot + c0;
                float* o1 = Out + (size_t)(r0 + 8) * Ntot + c0;
                if (ADDRES) {
                    float2 x0 = *(const float2*)(Res + (size_t)r0 * Ntot + c0);
                    float2 x1 = *(const float2*)(Res + (size_t)(r0 + 8) * Ntot + c0);
                    v0.x += x0.x; v0.y += x0.y;
                    v1.x += x1.x; v1.y += x1.y;
                }
                *(float2*)o0 = v0;
                *(float2*)o1 = v1;
            }
        }
    }
}

// ---------------- weight converts ----------------
__global__ void cvtW1(const float* __restrict__ W) {
    int idx = blockIdx.x * 256 + threadIdx.x;
    if (idx >= NPAD1 * DD) return;
    int r = idx / DD;
    g_w1h[idx] = (r < DIPc) ? __float2half(W[idx]) : __half(0.f);
}
__global__ void cvtW2(const float* __restrict__ W) {
    int idx = blockIdx.x * 256 + threadIdx.x;
    if (idx >= DD * DIc) return;
    g_w2h[idx] = __float2half(W[idx]);
}

// ---------------- LayerNorm (half out) ----------------
__global__ void ln_kernel(const float* __restrict__ x,
                          const float* __restrict__ w,
                          const float* __restrict__ b) {
    int row = blockIdx.x;
    const float* xr = x + (size_t)row * DD;
    float s = 0.f, s2 = 0.f;
    for (int i = threadIdx.x; i < DD; i += 256) {
        float v = xr[i];
        s += v; s2 += v * v;
    }
    __shared__ float red0[8], red1[8];
    for (int o = 16; o; o >>= 1) {
        s  += __shfl_xor_sync(0xffffffffu, s,  o);
        s2 += __shfl_xor_sync(0xffffffffu, s2, o);
    }
    int warp = threadIdx.x >> 5, lane = threadIdx.x & 31;
    if (lane == 0) { red0[warp] = s; red1[warp] = s2; }
    __syncthreads();
    if (warp == 0) {
        s  = (lane < 8) ? red0[lane] : 0.f;
        s2 = (lane < 8) ? red1[lane] : 0.f;
        for (int o = 4; o; o >>= 1) {
            s  += __shfl_xor_sync(0xffffffffu, s,  o);
            s2 += __shfl_xor_sync(0xffffffffu, s2, o);
        }
        if (lane == 0) { red0[0] = s; red1[0] = s2; }
    }
    __syncthreads();
    float mu  = red0[0] * (1.f / DD);
    float var = red1[0] * (1.f / DD) - mu * mu;
    float rs  = rsqrtf(var + 1e-5f);
    __half* o = g_xnh + (size_t)row * DD;
    for (int i = threadIdx.x; i < DD; i += 256)
        o[i] = __float2half((xr[i] - mu) * rs * w[i] + b[i]);
}

// ---------------- depthwise causal conv(K=4) + SiLU, sliding window ----------------
// grid: (CDc/128, BB * 8 L-chunks); thread owns one channel, walks 512 steps.
__global__ void conv_kernel(const float* __restrict__ cw,
                            const float* __restrict__ cb) {
    int c  = blockIdx.x * 128 + threadIdx.x;
    int bz = blockIdx.y;
    int b  = bz >> 3, lc = bz & 7;
    int l0 = lc * 512;
    const float* src = g_zx + (size_t)b * LL * DIPc + DIc + c;
    float w0 = cw[c * 4], w1 = cw[c * 4 + 1], w2 = cw[c * 4 + 2], w3 = cw[c * 4 + 3];
    float bias = cb[c];
    float x0 = 0.f, x1 = 0.f, x2 = 0.f;
    if (l0 >= 3) {
        x0 = src[(size_t)(l0 - 3) * DIPc];
        x1 = src[(size_t)(l0 - 2) * DIPc];
        x2 = src[(size_t)(l0 - 1) * DIPc];
    }
    float* dst = g_xbc + (size_t)(b * LL + l0) * CDc + c;
#pragma unroll 4
    for (int i = 0; i < 512; i++) {
        float x3 = src[(size_t)(l0 + i) * DIPc];
        float s = bias + w0 * x0 + w1 * x1 + w2 * x2 + w3 * x3;
        dst[(size_t)i * CDc] = s / (1.f + __expf(-s));
        x0 = x1; x1 = x2; x2 = x3;
    }
}

// ---------------- selective scan (dt/dA fused), 64-step tiles ----------------
__global__ void __launch_bounds__(256) scan_kernel(const float* __restrict__ D_skip,
                                                   const float* __restrict__ dt_bias,
                                                   const float* __restrict__ A_log) {
    int bx = blockIdx.x;
    int b  = bx / (HHc * 2);
    int rem = bx % (HHc * 2);
    int h  = rem >> 1;
    int ph = rem & 1;
    int tid = threadIdx.x;
    int pl = tid >> 3;
    int q  = tid & 7;
    int n0 = q * 8;

    __shared__ float sx[64][32];
    __shared__ float sB[64][64];
    __shared__ float sC[64][64];
    __shared__ float sy[64][32];
    __shared__ float sdA[64], sdt[64];

    float hreg[8];
#pragma unroll
    for (int j = 0; j < 8; j++) hreg[j] = 0.f;

    float ds = D_skip[h];
    float aexp = __expf(A_log[h]);
    float dbias = dt_bias[h];
    size_t rowbase = (size_t)b * LL;
    int pcol = h * PP + ph * 32;

    for (int l0 = 0; l0 < LL; l0 += 64) {
        // stage x: 64 rows x 8 float4
        for (int i = tid; i < 64 * 8; i += 256) {
            int s = i >> 3, j4 = i & 7;
            *(float4*)&sx[s][j4 * 4] =
                *(const float4*)&g_xbc[(rowbase + l0 + s) * CDc + pcol + j4 * 4];
        }
        // stage B/C: 64 rows x 16 float4 each
        for (int i = tid; i < 64 * 16; i += 256) {
            int s = i >> 4, j4 = i & 15;
            const float* base = &g_xbc[(rowbase + l0 + s) * CDc + DIc];
            *(float4*)&sB[s][j4 * 4] = *(const float4*)(base + j4 * 4);
            *(float4*)&sC[s][j4 * 4] = *(const float4*)(base + NE + j4 * 4);
        }
        if (tid < 64) {
            float raw = g_zx[(rowbase + l0 + tid) * DIPc + (DIc + CDc) + h] + dbias;
            float dtv = (raw > 20.f) ? raw : log1pf(__expf(raw));
            sdt[tid] = dtv;
            sdA[tid] = __expf(-aexp * dtv);
        }
        __syncthreads();

#pragma unroll 4
        for (int s = 0; s < 64; s++) {
            float a  = sdA[s];
            float d  = sdt[s];
            float xv = sx[s][pl];
            float u  = d * xv;
            float4 b0 = *reinterpret_cast<const float4*>(&sB[s][n0]);
            float4 b1 = *reinterpret_cast<const float4*>(&sB[s][n0 + 4]);
            float4 c0 = *reinterpret_cast<const float4*>(&sC[s][n0]);
            float4 c1 = *reinterpret_cast<const float4*>(&sC[s][n0 + 4]);
            float acc = 0.f;
            hreg[0] = hreg[0] * a + u * b0.x; acc += hreg[0] * c0.x;
            hreg[1] = hreg[1] * a + u * b0.y; acc += hreg[1] * c0.y;
            hreg[2] = hreg[2] * a + u * b0.z; acc += hreg[2] * c0.z;
            hreg[3] = hreg[3] * a + u * b0.w; acc += hreg[3] * c0.w;
            hreg[4] = hreg[4] * a + u * b1.x; acc += hreg[4] * c1.x;
            hreg[5] = hreg[5] * a + u * b1.y; acc += hreg[5] * c1.y;
            hreg[6] = hreg[6] * a + u * b1.z; acc += hreg[6] * c1.z;
            hreg[7] = hreg[7] * a + u * b1.w; acc += hreg[7] * c1.w;
            acc += __shfl_xor_sync(0xffffffffu, acc, 1);
            acc += __shfl_xor_sync(0xffffffffu, acc, 2);
            acc += __shfl_xor_sync(0xffffffffu, acc, 4);
            if (q == 0) sy[s][pl] = acc + ds * xv;
        }
        __syncthreads();
        for (int i = tid; i < 64 * 8; i += 256) {
            int s = i >> 3, j4 = i & 7;
            *(float4*)&g_y[(rowbase + l0 + s) * DIc + pcol + j4 * 4] =
                *(const float4*)&sy[s][j4 * 4];
        }
        __syncthreads();
    }
}

// ---------------- gate + RMSNorm (half out) ----------------
__global__ void gate_kernel(const float* __restrict__ norm_w) {
    int row = blockIdx.x;
    int tid = threadIdx.x;
    const float* z = g_zx + (size_t)row * DIPc;
    const float* y = g_y + (size_t)row * DIc;
    __half* o = g_gh + (size_t)row * DIc;
    float t[6];
    float s2 = 0.f;
#pragma unroll
    for (int r = 0; r < 6; r++) {
        int i = tid + r * 256;
        float zz = z[i];
        float sig = 1.f / (1.f + __expf(-zz));
        float v = y[i] * zz * sig;
        t[r] = v;
        s2 += v * v;
    }
    __shared__ float red[8];
    for (int o2 = 16; o2; o2 >>= 1) s2 += __shfl_xor_sync(0xffffffffu, s2, o2);
    int warp = tid >> 5, lane = tid & 31;
    if (lane == 0) red[warp] = s2;
    __syncthreads();
    if (warp == 0) {
        s2 = (lane < 8) ? red[lane] : 0.f;
        for (int o2 = 4; o2; o2 >>= 1) s2 += __shfl_xor_sync(0xffffffffu, s2, o2);
        if (lane == 0) red[0] = s2;
    }
    __syncthreads();
    float scale = rsqrtf(red[0] * (1.f / DIc) + 1e-5f);
#pragma unroll
    for (int r = 0; r < 6; r++) {
        int i = tid + r * 256;
        o[i] = __float2half(t[r] * scale * norm_w[i]);
    }
}

// ---------------- launch ----------------
extern "C" void kernel_launch(void* const* d_in, const int* in_sizes, int n_in,
                              void* d_out, int out_size) {
    const float* x       = (const float*)d_in[0];
    const float* ln_w    = (const float*)d_in[1];
    const float* ln_b    = (const float*)d_in[2];
    const float* Win     = (const float*)d_in[3];
    const float* conv_w  = (const float*)d_in[4];
    const float* conv_b  = (const float*)d_in[5];
    const float* dt_bias = (const float*)d_in[6];
    const float* A_log   = (const float*)d_in[7];
    const float* D_skip  = (const float*)d_in[8];
    const float* norm_w  = (const float*)d_in[9];
    const float* Wout    = (const float*)d_in[10];
    float* out = (float*)d_out;

    float*  zx_ptr  = nullptr; cudaGetSymbolAddress((void**)&zx_ptr,  g_zx);
    __half* xnh_ptr = nullptr; cudaGetSymbolAddress((void**)&xnh_ptr, g_xnh);
    __half* gh_ptr  = nullptr; cudaGetSymbolAddress((void**)&gh_ptr,  g_gh);
    __half* w1h_ptr = nullptr; cudaGetSymbolAddress((void**)&w1h_ptr, g_w1h);
    __half* w2h_ptr = nullptr; cudaGetSymbolAddress((void**)&w2h_ptr, g_w2h);

    cudaFuncSetAttribute((const void*)gemm_h<DD,  false>,
                         cudaFuncAttributeMaxDynamicSharedMemorySize, GSMEM);
    cudaFuncSetAttribute((const void*)gemm_h<DIc, true>,
                         cudaFuncAttributeMaxDynamicSharedMemorySize, GSMEM);

    // 0-1. weight convert (half, pad Win rows to 3328)
    cvtW1<<<(NPAD1 * DD + 255) / 256, 256>>>(Win);
    cvtW2<<<(DD * DIc + 255) / 256, 256>>>(Wout);
    // 2. LayerNorm (half out)
    ln_kernel<<<MROWS, 256>>>(x, ln_w, ln_b);
    // 3. GEMM1: zxbcdt = xn @ Win^T  (M=32768, K=768, N=3224)
    gemm_h<DD, false><<<dim3(NPAD1 / 128, MROWS / 128), 256, GSMEM>>>(
        xnh_ptr, w1h_ptr, nullptr, zx_ptr, DIPc);
    // 4. conv + silu (sliding window)
    conv_kernel<<<dim3(CDc / 128, BB * 8), 128>>>(conv_w, conv_b);
    // 5. selective scan (dt fused)
    scan_kernel<<<BB * HHc * 2, 256>>>(D_skip, dt_bias, A_log);
    // 6. gate + RMSNorm (half out)
    gate_kernel<<<MROWS, 256>>>(norm_w);
    // 7. GEMM2: out = g @ Wout^T + x  (M=32768, K=1536, N=768)
    gemm_h<DIc, true><<<dim3(DD / 128, MROWS / 128), 256, GSMEM>>>(
        gh_ptr, w2h_ptr, x, out, DD);
}